// round 11
// baseline (speedup 1.0000x reference)
#include <cuda_runtime.h>

#define DEVINL __device__ __forceinline__

typedef unsigned long long u64;

struct cplx { float x, y; };

DEVINL cplx cmul(cplx a, cplx b) {
    cplx r;
    r.x = fmaf(a.x, b.x, -a.y * b.y);
    r.y = fmaf(a.x, b.y,  a.y * b.x);
    return r;
}

// ---- packed f32x2 helpers ----
DEVINL u64 pk(float lo, float hi) {
    u64 r; asm("mov.b64 %0,{%1,%2};" : "=l"(r) : "f"(lo), "f"(hi)); return r;
}
DEVINL void upk(u64 a, float& lo, float& hi) {
    asm("mov.b64 {%0,%1},%2;" : "=f"(lo), "=f"(hi) : "l"(a));
}
DEVINL u64 spl(float v) { return pk(v, v); }
DEVINL u64 fma2(u64 a, u64 b, u64 c) {
    u64 r; asm("fma.rn.f32x2 %0,%1,%2,%3;" : "=l"(r) : "l"(a), "l"(b), "l"(c)); return r;
}
DEVINL u64 mul2(u64 a, u64 b) {
    u64 r; asm("mul.rn.f32x2 %0,%1,%2;" : "=l"(r) : "l"(a), "l"(b)); return r;
}
DEVINL u64 add2(u64 a, u64 b) {
    u64 r; asm("add.rn.f32x2 %0,%1,%2;" : "=l"(r) : "l"(a), "l"(b)); return r;
}
DEVINL u64 neg2(u64 a) { return a ^ 0x8000000080000000ULL; }
DEVINL u64 swp(u64 a) { float x, y; upk(a, x, y); return pk(y, x); }
// balanced 4-term dot: (a*b + c*d) + (e*f + g*h) — depth 3, 2-way ILP
DEVINL u64 cdot4(u64 a, u64 b, u64 c, u64 d, u64 e, u64 f, u64 g, u64 h) {
    return add2(fma2(a, b, mul2(c, d)), fma2(e, f, mul2(g, h)));
}

// g_U[0][q]: full RZ*RY*RX (layer 0).
// g_U[1][q]: RY*RX only (layer-1 RZ drops out before |.|^2). SU(2).
__device__ float g_U[2][8][8];
// Pre-packed gate constants:
// [0..5]  U3:  T0x T0y nT0y T1x T1y nT1y
// [6..11] U7:  CAx CAy nCAy CBx CBy nCBy
// [12..14] O3: nzp nxp nyp
__device__ u64 g_Cpk[16];

__global__ void qnn_setup(const float* __restrict__ w) {
    int i = threadIdx.x;
    if (i >= 16) return;
    int l = i >> 3, q = i & 7;
    float a = w[(l * 8 + q) * 3 + 0];
    float b = w[(l * 8 + q) * 3 + 1];
    float c = w[(l * 8 + q) * 3 + 2];
    float sa, ca; sincosf(0.5f * a, &sa, &ca);
    float sb, cb; sincosf(0.5f * b, &sb, &cb);
    float sc, cc; sincosf(0.5f * c, &sc, &cc);
    cplx m00 = {  cb * ca,  sb * sa };
    cplx m01 = { -sb * ca, -cb * sa };
    cplx m10 = {  sb * ca, -cb * sa };
    cplx m11 = {  cb * ca, -sb * sa };
    cplx u00, u01, u10, u11;
    if (l == 0) {
        cplx e0 = { cc, -sc };
        cplx e1 = { cc,  sc };
        u00 = cmul(e0, m00); u01 = cmul(e0, m01);
        u10 = cmul(e1, m10); u11 = cmul(e1, m11);
    } else {
        u00 = m00; u01 = m01; u10 = m10; u11 = m11;   // RZ dropped
    }
    if (l == 1 && q == 3) {
        g_Cpk[0] = pk(m00.x,  m00.x);
        g_Cpk[1] = pk(m00.y, -m00.y);
        g_Cpk[2] = pk(-m00.y, m00.y);
        g_Cpk[3] = pk(m01.x, -m01.x);
        g_Cpk[4] = pk(m01.y,  m01.y);
        g_Cpk[5] = pk(-m01.y, -m01.y);
    }
    if (l == 1 && q == 7) {
        g_Cpk[6]  = pk(m00.x,  m00.x);
        g_Cpk[7]  = pk(m00.y, -m00.y);
        g_Cpk[8]  = pk(-m00.y, m00.y);
        g_Cpk[9]  = pk(m01.x, -m01.x);
        g_Cpk[10] = pk(m01.y,  m01.y);
        g_Cpk[11] = pk(-m01.y, -m01.y);
    }
    if (l == 1 && q == 4) {
        // O3 = M^dag Z M with M = RY*RX
        float nz = (m00.x*m00.x + m00.y*m00.y) - (m10.x*m10.x + m10.y*m10.y);
        float cr = (m00.x*m01.x + m00.y*m01.y) - (m10.x*m11.x + m10.y*m11.y);
        float ci = (m00.x*m01.y - m00.y*m01.x) - (m10.x*m11.y - m10.y*m11.x);
        g_Cpk[12] = pk(nz, nz);
        g_Cpk[13] = pk(2.0f * cr, 2.0f * cr);      // 2*nx
        g_Cpk[14] = pk(-2.0f * ci, -2.0f * ci);    // 2*ny
    }
    float* dst = g_U[l][q];
    dst[0] = u00.x; dst[1] = u00.y; dst[2] = u01.x; dst[3] = u01.y;
    dst[4] = u10.x; dst[5] = u10.y; dst[6] = u11.x; dst[7] = u11.y;
}

// Layout: 8 lanes per sample (g = lane>>3, t = lane&7).
// Full amp index bits [7..0] = [t2 t1 t0 | j4 j3 j2 j1 | j0], wire w <-> bit 7-w.
__global__ void __launch_bounds__(256, 2) qnn_main(
    const float* __restrict__ x, float* __restrict__ out, int B)
{
    const unsigned FULL = 0xffffffffu;
    int L = threadIdx.x & 31;
    int warp = blockIdx.x * (blockDim.x >> 5) + (threadIdx.x >> 5);
    int g = L >> 3;
    int t = L & 7;
    int b = warp * 4 + g;
    bool valid = (b < B);

    // hoist constant loads so their latency overlaps the front math
    u64 T0x = g_Cpk[0], T0y = g_Cpk[1], nT0y = g_Cpk[2];
    u64 T1x = g_Cpk[3], T1y = g_Cpk[4], nT1y = g_Cpk[5];
    u64 CAx = g_Cpk[6], CAy = g_Cpk[7], nCAy = g_Cpk[8];
    u64 CBx = g_Cpk[9], CBy = g_Cpk[10], nCBy = g_Cpk[11];
    u64 nzp = g_Cpk[12], nxp = g_Cpk[13], nyp = g_Cpk[14];
    float4 u0a = *reinterpret_cast<const float4*>(g_U[0][t]);       // u00,u01
    float4 u0b = *reinterpret_cast<const float4*>(g_U[0][t] + 4);   // u10,u11
    int a_ = (t >> 2) & 1, b_ = (t >> 1) & 1, c_ = t & 1;   // t2,t1,t0
    float4 Av = *reinterpret_cast<const float4*>(g_U[1][0] + 4 * a_);
    float4 Bv = *reinterpret_cast<const float4*>(g_U[1][1] + 4 * b_);
    float4 Cv = *reinterpret_cast<const float4*>(g_U[1][2] + 4 * c_);
    float4 u6lo = *reinterpret_cast<const float4*>(g_U[1][6]);
    float4 u6hi = *reinterpret_cast<const float4*>(g_U[1][6] + 4);
    float4 u5lo = *reinterpret_cast<const float4*>(g_U[1][5]);
    float4 u5hi = *reinterpret_cast<const float4*>(g_U[1][5] + 4);

    float xv = valid ? x[b * 8 + t] : 0.0f;
    float s, c;
    __sincosf(0.5f * xv, &s, &c);

    // V_q = U[0][q]*RX(x_q) column 0 (embedding fused into layer-0).
    cplx myv0, myv1;
    myv0.x = fmaf(c, u0a.x,  s * u0a.w);
    myv0.y = fmaf(c, u0a.y, -s * u0a.z);
    myv1.x = fmaf(c, u0b.x,  s * u0b.w);
    myv1.y = fmaf(c, u0b.y, -s * u0b.z);

    cplx va[8], vb[8];
    int base = L & ~7;
#pragma unroll
    for (int q = 0; q < 8; q++) {
        int src = base | q;
        va[q].x = __shfl_sync(FULL, myv0.x, src);
        va[q].y = __shfl_sync(FULL, myv0.y, src);
        vb[q].x = __shfl_sync(FULL, myv1.x, src);
        vb[q].y = __shfl_sync(FULL, myv1.y, src);
    }

    // ============================================================
    // Symbolic layer-1 gates on wires 0,1,2,3 against the product
    // state (CNOT ring as XOR args). Result Q[j4][j3] packed over j0.
    // ============================================================
    cplx A0 = { Av.x, Av.y }, A1 = { Av.z, Av.w };
    cplx B0 = { Bv.x, Bv.y }, B1 = { Bv.z, Bv.w };
    cplx C0 = { Cv.x, Cv.y }, C1 = { Cv.z, Cv.w };

    // w[s][r] = U2[c][s]*v2[r^s]
    u64 V2X = pk(va[2].x, vb[2].x), V2Y = pk(va[2].y, vb[2].y);
    u64 V2Xs = swp(V2X), V2Ys = swp(V2Y);
    u64 WAX = fma2(spl(C0.x), V2X,  mul2(spl(-C0.y), V2Y));
    u64 WAY = fma2(spl(C0.x), V2Y,  mul2(spl(C0.y),  V2X));
    u64 WBX = fma2(spl(C1.x), V2Xs, mul2(spl(-C1.y), V2Ys));
    u64 WBY = fma2(spl(C1.x), V2Ys, mul2(spl(C1.y),  V2Xs));
    float w00x, w01x, w00y, w01y, w10x, w11x, w10y, w11y;
    upk(WAX, w00x, w01x); upk(WAY, w00y, w01y);
    upk(WBX, w10x, w11x); upk(WBY, w10y, w11y);

    // z[r][e] = U1[b][r]*v1[e^r]
    u64 V1X = pk(va[1].x, vb[1].x), V1Y = pk(va[1].y, vb[1].y);
    u64 V1Xs = swp(V1X), V1Ys = swp(V1Y);
    u64 ZAX = fma2(spl(B0.x), V1X,  mul2(spl(-B0.y), V1Y));
    u64 ZAY = fma2(spl(B0.x), V1Y,  mul2(spl(B0.y),  V1X));
    u64 ZBX = fma2(spl(B1.x), V1Xs, mul2(spl(-B1.y), V1Ys));
    u64 ZBY = fma2(spl(B1.x), V1Ys, mul2(spl(B1.y),  V1Xs));

    // zz[r][e] = v0[e]*z[r][e]  (packed over e)
    u64 V0X = pk(va[0].x, vb[0].x), V0Y = pk(va[0].y, vb[0].y);
    u64 ZZAX = fma2(ZAX, V0X, mul2(neg2(ZAY), V0Y));
    u64 ZZAY = fma2(ZAX, V0Y, mul2(ZAY, V0X));
    u64 ZZBX = fma2(ZBX, V0X, mul2(neg2(ZBY), V0Y));
    u64 ZZBY = fma2(ZBX, V0Y, mul2(ZBY, V0X));

    // ZP[r] packed over j0 = A0*zz[r][j0] + A1*zz[r][j0^1]
    u64 a0x = spl(A0.x), na0y = spl(-A0.y), a0y = spl(A0.y);
    u64 a1x = spl(A1.x), na1y = spl(-A1.y), a1y = spl(A1.y);
    u64 sZZAX = swp(ZZAX), sZZAY = swp(ZZAY);
    u64 sZZBX = swp(ZZBX), sZZBY = swp(ZZBY);
    u64 ZPAX = cdot4(a0x, ZZAX, na0y, ZZAY, a1x, sZZAX, na1y, sZZAY);
    u64 ZPAY = cdot4(a0x, ZZAY, a0y, ZZAX, a1x, sZZAY, a1y, sZZAX);
    u64 ZPBX = cdot4(a0x, ZZBX, na0y, ZZBY, a1x, sZZBX, na1y, sZZBY);
    u64 ZPBY = cdot4(a0x, ZZBY, a0y, ZZBX, a1x, sZZBY, a1y, sZZBX);
    float zp0x[2], zp0y[2], zp1x[2], zp1y[2];   // [j0]
    upk(ZPAX, zp0x[0], zp0x[1]); upk(ZPAY, zp0y[0], zp0y[1]);
    upk(ZPBX, zp1x[0], zp1x[1]); upk(ZPBY, zp1y[0], zp1y[1]);

    // packed over j4': V3s0 = v3[j4'], V3s1 = v3[1^j4']
    u64 V30X = pk(va[3].x, vb[3].x), V30Y = pk(va[3].y, vb[3].y);
    u64 V31X = swp(V30X),            V31Y = swp(V30Y);

    // M[r](j4') = sum_s w[s][r] v3[s^j4']
    u64 MX[2], MY[2];
#pragma unroll
    for (int r = 0; r < 2; r++) {
        float s0x = r ? w01x : w00x, s0y = r ? w01y : w00y;
        float s1x = r ? w11x : w10x, s1y = r ? w11y : w10y;
        MX[r] = cdot4(spl(s0x), V30X, spl(-s0y), V30Y, spl(s1x), V31X, spl(-s1y), V31Y);
        MY[r] = cdot4(spl(s0x), V30Y, spl(s0y), V30X, spl(s1x), V31Y, spl(s1y), V31X);
    }

    // mj[r][j3](j4') = M[r](j4') * v4[j4'^j3]
    u64 V40X = pk(va[4].x, vb[4].x), V40Y = pk(va[4].y, vb[4].y);
    u64 V41X = swp(V40X),            V41Y = swp(V40Y);
    // g[r][j3](j4) = sum_{j4'} U3[j4,j4'] mj[r][j3](j4')
    u64 nMY0 = neg2(MY[0]), nMY1 = neg2(MY[1]);
    u64 GX[2][2], GY[2][2];
#pragma unroll
    for (int r = 0; r < 2; r++) {
        u64 nMY = r ? nMY1 : nMY0;
#pragma unroll
        for (int j3 = 0; j3 < 2; j3++) {
            u64 vx = j3 ? V41X : V40X, vy = j3 ? V41Y : V40Y;
            u64 mX = fma2(MX[r], vx, mul2(nMY, vy));
            u64 mY = fma2(MX[r], vy, mul2(MY[r], vx));
            u64 smX = swp(mX), smY = swp(mY);
            GX[r][j3] = cdot4(T0x, mX, nT0y, mY, T1x, smX, nT1y, smY);
            GY[r][j3] = cdot4(T0x, mY, T0y, mX, T1x, smY, T1y, smX);
        }
    }

    // P[j0][j3] = sum_r ZP[r][j0] (x) G[r][j3]  (packed over j4)
    u64 PX[2][2], PY[2][2];
#pragma unroll
    for (int j0 = 0; j0 < 2; j0++) {
        u64 c0x = spl(zp0x[j0]), nc0y = spl(-zp0y[j0]), c0y = spl(zp0y[j0]);
        u64 c1x = spl(zp1x[j0]), nc1y = spl(-zp1y[j0]), c1y = spl(zp1y[j0]);
#pragma unroll
        for (int j3 = 0; j3 < 2; j3++) {
            PX[j0][j3] = cdot4(c0x, GX[0][j3], nc0y, GY[0][j3],
                               c1x, GX[1][j3], nc1y, GY[1][j3]);
            PY[j0][j3] = cdot4(c0x, GY[0][j3], c0y, GX[0][j3],
                               c1x, GY[1][j3], c1y, GX[1][j3]);
        }
    }
    // transpose to packed-over-j0: Q[j4][j3]
    u64 QX[2][2], QY[2][2];
#pragma unroll
    for (int j3 = 0; j3 < 2; j3++) {
        float p00, p01, p10, p11;
        upk(PX[0][j3], p00, p01); upk(PX[1][j3], p10, p11);
        QX[0][j3] = pk(p00, p10); QX[1][j3] = pk(p01, p11);
        upk(PY[0][j3], p00, p01); upk(PY[1][j3], p10, p11);
        QY[0][j3] = pk(p00, p10); QY[1][j3] = pk(p01, p11);
    }

    // U7 premix (fused): QA = CA o Q ; QB = CB o swp(Q)
    u64 QAX[2][2], QAY[2][2], QBX[2][2], QBY[2][2];
#pragma unroll
    for (int j4 = 0; j4 < 2; j4++) {
#pragma unroll
        for (int j3 = 0; j3 < 2; j3++) {
            u64 qx = QX[j4][j3], qy = QY[j4][j3];
            u64 sqx = swp(qx), sqy = swp(qy);
            QAX[j4][j3] = fma2(CAx, qx, mul2(nCAy, qy));
            QAY[j4][j3] = fma2(CAx, qy, mul2(CAy, qx));
            QBX[j4][j3] = fma2(CBx, sqx, mul2(nCBy, sqy));
            QBY[j4][j3] = fma2(CBx, sqy, mul2(CBy, sqx));
        }
    }

    // ============================================================
    // Chain with U5/U6 folded:
    //   W67[j2'][j1](j0) = sum_{j1'} U6[j1,j1'] v6[j2'^j1'] v7[j1'^j0]
    //   CT[j3][j2][j1](j0) = sum_{j2'} U5[j2,j2'] v5[j3^j2'] W67[j2'][j1]
    //   amp = QA (.) CT + QB (.) swp(CT); measurement fused in-loop.
    // ============================================================
    u64 V7X[2], V7Y[2];
    V7X[0] = pk(va[7].x, vb[7].x); V7Y[0] = pk(va[7].y, vb[7].y);
    V7X[1] = swp(V7X[0]);          V7Y[1] = swp(V7Y[0]);

    // e-factory: E0[j1] over j2' = U6[j1][0]*v6[j2']; E1[j1] over j2' = U6[j1][1]*v6[1^j2']
    u64 V6X = pk(va[6].x, vb[6].x), V6Y = pk(va[6].y, vb[6].y);
    u64 V6Xs = swp(V6X), V6Ys = swp(V6Y);
    float e0x[2][2], e0y[2][2], e1x[2][2], e1y[2][2];   // [j1][j2']
#pragma unroll
    for (int j1 = 0; j1 < 2; j1++) {
        float g0 = j1 ? u6hi.x : u6lo.x, g1 = j1 ? u6hi.y : u6lo.y;
        float g2 = j1 ? u6hi.z : u6lo.z, g3 = j1 ? u6hi.w : u6lo.w;
        u64 E0X = fma2(spl(g0), V6X,  mul2(spl(-g1), V6Y));
        u64 E0Y = fma2(spl(g0), V6Y,  mul2(spl(g1),  V6X));
        u64 E1X = fma2(spl(g2), V6Xs, mul2(spl(-g3), V6Ys));
        u64 E1Y = fma2(spl(g2), V6Ys, mul2(spl(g3),  V6Xs));
        upk(E0X, e0x[j1][0], e0x[j1][1]); upk(E0Y, e0y[j1][0], e0y[j1][1]);
        upk(E1X, e1x[j1][0], e1x[j1][1]); upk(E1Y, e1y[j1][0], e1y[j1][1]);
    }

    u64 WX[2][2], WY[2][2];   // [j2'][j1]
#pragma unroll
    for (int j2p = 0; j2p < 2; j2p++) {
#pragma unroll
        for (int j1 = 0; j1 < 2; j1++) {
            u64 b0x = spl(e0x[j1][j2p]), b0y = spl(e0y[j1][j2p]);
            u64 b1x = spl(e1x[j1][j2p]), b1y = spl(e1y[j1][j2p]);
            WX[j2p][j1] = cdot4(b0x, V7X[0], neg2(b0y), V7Y[0],
                                b1x, V7X[1], neg2(b1y), V7Y[1]);
            WY[j2p][j1] = cdot4(b0x, V7Y[0], b0y, V7X[0],
                                b1x, V7Y[1], b1y, V7X[1]);
        }
    }

    // f-factory: F0[j2] over j3 = U5[j2][0]*v5[j3]; F1[j2] over j3 = U5[j2][1]*v5[1^j3]
    u64 V5X = pk(va[5].x, vb[5].x), V5Y = pk(va[5].y, vb[5].y);
    u64 V5Xs = swp(V5X), V5Ys = swp(V5Y);
    float f0x[2][2], f0y[2][2], f1x[2][2], f1y[2][2];   // [j2][j3]
#pragma unroll
    for (int j2 = 0; j2 < 2; j2++) {
        float g0 = j2 ? u5hi.x : u5lo.x, g1 = j2 ? u5hi.y : u5lo.y;
        float g2 = j2 ? u5hi.z : u5lo.z, g3 = j2 ? u5hi.w : u5lo.w;
        u64 F0X = fma2(spl(g0), V5X,  mul2(spl(-g1), V5Y));
        u64 F0Y = fma2(spl(g0), V5Y,  mul2(spl(g1),  V5X));
        u64 F1X = fma2(spl(g2), V5Xs, mul2(spl(-g3), V5Ys));
        u64 F1Y = fma2(spl(g2), V5Ys, mul2(spl(g3),  V5Xs));
        upk(F0X, f0x[j2][0], f0x[j2][1]); upk(F0Y, f0y[j2][0], f0y[j2][1]);
        upk(F1X, f1x[j2][0], f1x[j2][1]); upk(F1Y, f1y[j2][0], f1y[j2][1]);
    }

    // ---- fused assembly + measurement ----
    u64 m1 = spl(-1.0f);
    u64 S00p = 0, S10p = 0, S18p = 0, S1Cp = 0, S1Ep = 0;   // 0 == packed (0.0f,0.0f)

#pragma unroll
    for (int j2 = 0; j2 < 2; j2++) {
#pragma unroll
        for (int j1 = 0; j1 < 2; j1++) {
            u64 CTX[2], CTY[2], CTXs[2], CTYs[2];
#pragma unroll
            for (int j3 = 0; j3 < 2; j3++) {
                u64 g0x = spl(f0x[j2][j3]), g0y = spl(f0y[j2][j3]), ng0y = spl(-f0y[j2][j3]);
                u64 g1x = spl(f1x[j2][j3]), g1y = spl(f1y[j2][j3]), ng1y = spl(-f1y[j2][j3]);
                CTX[j3] = cdot4(g0x, WX[0][j1], ng0y, WY[0][j1],
                                g1x, WX[1][j1], ng1y, WY[1][j1]);
                CTY[j3] = cdot4(g0x, WY[0][j1], g0y, WX[0][j1],
                                g1x, WY[1][j1], g1y, WX[1][j1]);
                CTXs[j3] = swp(CTX[j3]);
                CTYs[j3] = swp(CTY[j3]);
            }
#pragma unroll
            for (int j4 = 0; j4 < 2; j4++) {
                u64 X0 = cdot4(QAX[j4][0], CTX[0], QAY[j4][0], neg2(CTY[0]),
                               QBX[j4][0], CTXs[0], QBY[j4][0], neg2(CTYs[0]));
                u64 Y0 = cdot4(QAX[j4][0], CTY[0], QAY[j4][0], CTX[0],
                               QBX[j4][0], CTYs[0], QBY[j4][0], CTXs[0]);
                u64 X1 = cdot4(QAX[j4][1], CTX[1], QAY[j4][1], neg2(CTY[1]),
                               QBX[j4][1], CTXs[1], QBY[j4][1], neg2(CTYs[1]));
                u64 Y1 = cdot4(QAX[j4][1], CTY[1], QAY[j4][1], CTX[1],
                               QBX[j4][1], CTYs[1], QBY[j4][1], CTXs[1]);
                u64 PR0 = fma2(X0, X0, mul2(Y0, Y0));
                u64 PR1 = fma2(X1, X1, mul2(Y1, Y1));
                u64 SP3 = add2(PR0, PR1);
                u64 DP3 = fma2(m1, PR1, PR0);
                u64 CR = fma2(X0, X1, mul2(Y0, Y1));              // Re(a0* a1)
                u64 CI = fma2(X0, Y1, mul2(neg2(Y0), X1));        // Im(a0* a1)
                u64 T = fma2(nzp, DP3, fma2(nxp, CR, mul2(nyp, CI)));
                S00p = add2(S00p, SP3);
                S10p = j4 ? fma2(m1, SP3, S10p) : add2(S10p, SP3);
                S18p = j4 ? fma2(m1, T, S18p) : add2(S18p, T);
                S1Cp = (j4 ^ j2) ? fma2(m1, T, S1Cp) : add2(S1Cp, T);
                S1Ep = (j4 ^ j2 ^ j1) ? fma2(m1, T, S1Ep) : add2(S1Ep, T);
            }
        }
    }

    float lo, hi;
    upk(S00p, lo, hi); float S00 = lo + hi;
    upk(S10p, lo, hi); float S10 = lo + hi;
    upk(S18p, lo, hi); float S18 = lo + hi;
    upk(S1Cp, lo, hi); float S1C = lo + hi;
    upk(S1Ep, lo, hi); float S1E = lo + hi, S1F = lo - hi;

    float sg3 = ((__popc(t & 3) & 1) ? -1.0f : 1.0f);
    float sg6 = ((__popc(t & 6) & 1) ? -1.0f : 1.0f);
    float sg7 = ((__popc(t & 7) & 1) ? -1.0f : 1.0f);

    float r[8];
    r[0] = sg3 * S1F;   // Z0: mask 0x7F
    r[1] = sg6 * S00;   // Z1: mask 0xC0
    r[2] = sg7 * S00;   // Z2: mask 0xE0
    r[3] = sg7 * S10;   // 0xF0
    r[4] = sg7 * S18;   // 0xF8
    r[5] = sg7 * S1C;   // 0xFC
    r[6] = sg7 * S1E;   // 0xFE
    r[7] = sg7 * S1F;   // 0xFF

    // distributed transpose-reduction across the 8-lane group (7 shfls)
    int t0 = c_, t1 = b_, t2 = a_;
    float q4[4];
#pragma unroll
    for (int j = 0; j < 4; j++) {
        float keep = t0 ? r[2*j+1] : r[2*j];
        float send = t0 ? r[2*j]   : r[2*j+1];
        q4[j] = keep + __shfl_xor_sync(FULL, send, 1);
    }
    float q2[2];
#pragma unroll
    for (int j = 0; j < 2; j++) {
        float keep = t1 ? q4[2*j+1] : q4[2*j];
        float send = t1 ? q4[2*j]   : q4[2*j+1];
        q2[j] = keep + __shfl_xor_sync(FULL, send, 2);
    }
    float keep = t2 ? q2[1] : q2[0];
    float send = t2 ? q2[0] : q2[1];
    float res = keep + __shfl_xor_sync(FULL, send, 4);

    if (valid) out[b * 8 + t] = res;
}

extern "C" void kernel_launch(void* const* d_in, const int* in_sizes, int n_in,
                              void* d_out, int out_size)
{
    const float* x = (const float*)d_in[0];
    const float* w = (const float*)d_in[1];
    float* out = (float*)d_out;
    int B = in_sizes[0] / 8;

    qnn_setup<<<1, 32>>>(w);

    int warps = (B + 3) / 4;
    int blocks = (warps + 7) / 8;
    qnn_main<<<blocks, 256>>>(x, out, B);
}

// round 13
// speedup vs baseline: 1.0939x; 1.0939x over previous
#include <cuda_runtime.h>

#define DEVINL __device__ __forceinline__

typedef unsigned long long u64;

struct cplx { float x, y; };

DEVINL cplx cmul(cplx a, cplx b) {
    cplx r;
    r.x = fmaf(a.x, b.x, -a.y * b.y);
    r.y = fmaf(a.x, b.y,  a.y * b.x);
    return r;
}

// ---- packed f32x2 helpers ----
DEVINL u64 pk(float lo, float hi) {
    u64 r; asm("mov.b64 %0,{%1,%2};" : "=l"(r) : "f"(lo), "f"(hi)); return r;
}
DEVINL void upk(u64 a, float& lo, float& hi) {
    asm("mov.b64 {%0,%1},%2;" : "=f"(lo), "=f"(hi) : "l"(a));
}
DEVINL u64 spl(float v) { return pk(v, v); }
DEVINL u64 fma2(u64 a, u64 b, u64 c) {
    u64 r; asm("fma.rn.f32x2 %0,%1,%2,%3;" : "=l"(r) : "l"(a), "l"(b), "l"(c)); return r;
}
DEVINL u64 mul2(u64 a, u64 b) {
    u64 r; asm("mul.rn.f32x2 %0,%1,%2;" : "=l"(r) : "l"(a), "l"(b)); return r;
}
DEVINL u64 add2(u64 a, u64 b) {
    u64 r; asm("add.rn.f32x2 %0,%1,%2;" : "=l"(r) : "l"(a), "l"(b)); return r;
}
DEVINL u64 neg2(u64 a) { return a ^ 0x8000000080000000ULL; }
DEVINL u64 swp(u64 a) { float x, y; upk(a, x, y); return pk(y, x); }

// g_U[0][q]: full RZ*RY*RX (layer 0).
// g_U[1][q]: RY*RX only (layer-1 RZ drops out before |.|^2). SU(2).
__device__ float g_U[2][8][8];
// Pre-packed gate constants:
// [0..5]  U3:  T0x T0y nT0y T1x T1y nT1y
// [6..11] U7:  CAx CAy nCAy CBx CBy nCBy
// [12..14] O3: nzp nxp nyp
__device__ u64 g_Cpk[16];

__global__ void qnn_setup(const float* __restrict__ w) {
    int i = threadIdx.x;
    if (i >= 16) return;
    int l = i >> 3, q = i & 7;
    float a = w[(l * 8 + q) * 3 + 0];
    float b = w[(l * 8 + q) * 3 + 1];
    float c = w[(l * 8 + q) * 3 + 2];
    float sa, ca; sincosf(0.5f * a, &sa, &ca);
    float sb, cb; sincosf(0.5f * b, &sb, &cb);
    float sc, cc; sincosf(0.5f * c, &sc, &cc);
    cplx m00 = {  cb * ca,  sb * sa };
    cplx m01 = { -sb * ca, -cb * sa };
    cplx m10 = {  sb * ca, -cb * sa };
    cplx m11 = {  cb * ca, -sb * sa };
    cplx u00, u01, u10, u11;
    if (l == 0) {
        cplx e0 = { cc, -sc };
        cplx e1 = { cc,  sc };
        u00 = cmul(e0, m00); u01 = cmul(e0, m01);
        u10 = cmul(e1, m10); u11 = cmul(e1, m11);
    } else {
        u00 = m00; u01 = m01; u10 = m10; u11 = m11;   // RZ dropped
    }
    if (l == 1 && q == 3) {
        g_Cpk[0] = pk(m00.x,  m00.x);
        g_Cpk[1] = pk(m00.y, -m00.y);
        g_Cpk[2] = pk(-m00.y, m00.y);
        g_Cpk[3] = pk(m01.x, -m01.x);
        g_Cpk[4] = pk(m01.y,  m01.y);
        g_Cpk[5] = pk(-m01.y, -m01.y);
    }
    if (l == 1 && q == 7) {
        g_Cpk[6]  = pk(m00.x,  m00.x);
        g_Cpk[7]  = pk(m00.y, -m00.y);
        g_Cpk[8]  = pk(-m00.y, m00.y);
        g_Cpk[9]  = pk(m01.x, -m01.x);
        g_Cpk[10] = pk(m01.y,  m01.y);
        g_Cpk[11] = pk(-m01.y, -m01.y);
    }
    if (l == 1 && q == 4) {
        // O3 = M^dag Z M with M = RY*RX
        float nz = (m00.x*m00.x + m00.y*m00.y) - (m10.x*m10.x + m10.y*m10.y);
        float cr = (m00.x*m01.x + m00.y*m01.y) - (m10.x*m11.x + m10.y*m11.y);
        float ci = (m00.x*m01.y - m00.y*m01.x) - (m10.x*m11.y - m10.y*m11.x);
        g_Cpk[12] = pk(nz, nz);
        g_Cpk[13] = pk(2.0f * cr, 2.0f * cr);      // 2*nx
        g_Cpk[14] = pk(-2.0f * ci, -2.0f * ci);    // 2*ny
    }
    float* dst = g_U[l][q];
    dst[0] = u00.x; dst[1] = u00.y; dst[2] = u01.x; dst[3] = u01.y;
    dst[4] = u10.x; dst[5] = u10.y; dst[6] = u11.x; dst[7] = u11.y;
}

// Layout: 8 lanes per sample (g = lane>>3, t = lane&7).
// Full amp index bits [7..0] = [t2 t1 t0 | j4 j3 j2 j1 | j0], wire w <-> bit 7-w.
__global__ void __launch_bounds__(128, 5) qnn_main(
    const float* __restrict__ x, float* __restrict__ out, int B)
{
    const unsigned FULL = 0xffffffffu;
    int L = threadIdx.x & 31;
    int warp = blockIdx.x * (blockDim.x >> 5) + (threadIdx.x >> 5);
    int g = L >> 3;
    int t = L & 7;
    int b = warp * 4 + g;
    bool valid = (b < B);

    // hoist constant loads so their latency overlaps the front math
    u64 T0x = g_Cpk[0], T0y = g_Cpk[1], nT0y = g_Cpk[2];
    u64 T1x = g_Cpk[3], T1y = g_Cpk[4], nT1y = g_Cpk[5];
    u64 CAx = g_Cpk[6], CAy = g_Cpk[7], nCAy = g_Cpk[8];
    u64 CBx = g_Cpk[9], CBy = g_Cpk[10], nCBy = g_Cpk[11];
    u64 nzp = g_Cpk[12], nxp = g_Cpk[13], nyp = g_Cpk[14];
    float4 u0a = *reinterpret_cast<const float4*>(g_U[0][t]);       // u00,u01
    float4 u0b = *reinterpret_cast<const float4*>(g_U[0][t] + 4);   // u10,u11
    int a_ = (t >> 2) & 1, b_ = (t >> 1) & 1, c_ = t & 1;   // t2,t1,t0
    float4 Av = *reinterpret_cast<const float4*>(g_U[1][0] + 4 * a_);
    float4 Bv = *reinterpret_cast<const float4*>(g_U[1][1] + 4 * b_);
    float4 Cv = *reinterpret_cast<const float4*>(g_U[1][2] + 4 * c_);
    float4 u6lo = *reinterpret_cast<const float4*>(g_U[1][6]);
    float4 u6hi = *reinterpret_cast<const float4*>(g_U[1][6] + 4);
    float4 u5lo = *reinterpret_cast<const float4*>(g_U[1][5]);
    float4 u5hi = *reinterpret_cast<const float4*>(g_U[1][5] + 4);

    float xv = valid ? x[b * 8 + t] : 0.0f;
    float s, c;
    __sincosf(0.5f * xv, &s, &c);

    // V_q = U[0][q]*RX(x_q) column 0 (embedding fused into layer-0).
    cplx myv0, myv1;
    myv0.x = fmaf(c, u0a.x,  s * u0a.w);
    myv0.y = fmaf(c, u0a.y, -s * u0a.z);
    myv1.x = fmaf(c, u0b.x,  s * u0b.w);
    myv1.y = fmaf(c, u0b.y, -s * u0b.z);

    cplx va[8], vb[8];
    int base = L & ~7;
#pragma unroll
    for (int q = 0; q < 8; q++) {
        int src = base | q;
        va[q].x = __shfl_sync(FULL, myv0.x, src);
        va[q].y = __shfl_sync(FULL, myv0.y, src);
        vb[q].x = __shfl_sync(FULL, myv1.x, src);
        vb[q].y = __shfl_sync(FULL, myv1.y, src);
    }

    // ============================================================
    // Symbolic layer-1 gates on wires 0,1,2,3 against the product
    // state (CNOT ring as XOR args). Result Q[j4][j3] packed over j0.
    // ============================================================
    cplx A0 = { Av.x, Av.y }, A1 = { Av.z, Av.w };
    cplx B0 = { Bv.x, Bv.y }, B1 = { Bv.z, Bv.w };
    cplx C0 = { Cv.x, Cv.y }, C1 = { Cv.z, Cv.w };

    // w[s][r] = U2[c][s]*v2[r^s]
    u64 V2X = pk(va[2].x, vb[2].x), V2Y = pk(va[2].y, vb[2].y);
    u64 V2Xs = swp(V2X), V2Ys = swp(V2Y);
    u64 WAX = fma2(spl(C0.x), V2X,  mul2(spl(-C0.y), V2Y));
    u64 WAY = fma2(spl(C0.x), V2Y,  mul2(spl(C0.y),  V2X));
    u64 WBX = fma2(spl(C1.x), V2Xs, mul2(spl(-C1.y), V2Ys));
    u64 WBY = fma2(spl(C1.x), V2Ys, mul2(spl(C1.y),  V2Xs));
    float w00x, w01x, w00y, w01y, w10x, w11x, w10y, w11y;
    upk(WAX, w00x, w01x); upk(WAY, w00y, w01y);
    upk(WBX, w10x, w11x); upk(WBY, w10y, w11y);

    // z[r][e] = U1[b][r]*v1[e^r]
    u64 V1X = pk(va[1].x, vb[1].x), V1Y = pk(va[1].y, vb[1].y);
    u64 V1Xs = swp(V1X), V1Ys = swp(V1Y);
    u64 ZAX = fma2(spl(B0.x), V1X,  mul2(spl(-B0.y), V1Y));
    u64 ZAY = fma2(spl(B0.x), V1Y,  mul2(spl(B0.y),  V1X));
    u64 ZBX = fma2(spl(B1.x), V1Xs, mul2(spl(-B1.y), V1Ys));
    u64 ZBY = fma2(spl(B1.x), V1Ys, mul2(spl(B1.y),  V1Xs));

    // zz[r][e] = v0[e]*z[r][e]  (packed over e)
    u64 V0X = pk(va[0].x, vb[0].x), V0Y = pk(va[0].y, vb[0].y);
    u64 ZZAX = fma2(ZAX, V0X, mul2(neg2(ZAY), V0Y));
    u64 ZZAY = fma2(ZAX, V0Y, mul2(ZAY, V0X));
    u64 ZZBX = fma2(ZBX, V0X, mul2(neg2(ZBY), V0Y));
    u64 ZZBY = fma2(ZBX, V0Y, mul2(ZBY, V0X));

    // ZP[r] packed over j0 = A0*zz[r][j0] + A1*zz[r][j0^1]
    u64 a0x = spl(A0.x), na0y = spl(-A0.y), a0y = spl(A0.y);
    u64 a1x = spl(A1.x), na1y = spl(-A1.y), a1y = spl(A1.y);
    u64 sZZAX = swp(ZZAX), sZZAY = swp(ZZAY);
    u64 sZZBX = swp(ZZBX), sZZBY = swp(ZZBY);
    u64 ZPAX = fma2(a0x, ZZAX, fma2(na0y, ZZAY, fma2(a1x, sZZAX, mul2(na1y, sZZAY))));
    u64 ZPAY = fma2(a0x, ZZAY, fma2(a0y, ZZAX, fma2(a1x, sZZAY, mul2(a1y, sZZAX))));
    u64 ZPBX = fma2(a0x, ZZBX, fma2(na0y, ZZBY, fma2(a1x, sZZBX, mul2(na1y, sZZBY))));
    u64 ZPBY = fma2(a0x, ZZBY, fma2(a0y, ZZBX, fma2(a1x, sZZBY, mul2(a1y, sZZBX))));
    float zp0x[2], zp0y[2], zp1x[2], zp1y[2];   // [j0]
    upk(ZPAX, zp0x[0], zp0x[1]); upk(ZPAY, zp0y[0], zp0y[1]);
    upk(ZPBX, zp1x[0], zp1x[1]); upk(ZPBY, zp1y[0], zp1y[1]);

    // packed over j4': V3s0 = v3[j4'], V3s1 = v3[1^j4']
    u64 V30X = pk(va[3].x, vb[3].x), V30Y = pk(va[3].y, vb[3].y);
    u64 V31X = swp(V30X),            V31Y = swp(V30Y);

    // M[r](j4') = sum_s w[s][r] v3[s^j4']
    u64 MX[2], MY[2];
#pragma unroll
    for (int r = 0; r < 2; r++) {
        float s0x = r ? w01x : w00x, s0y = r ? w01y : w00y;
        float s1x = r ? w11x : w10x, s1y = r ? w11y : w10y;
        MX[r] = fma2(spl(s0x), V30X, fma2(spl(-s0y), V30Y,
                 fma2(spl(s1x), V31X, mul2(spl(-s1y), V31Y))));
        MY[r] = fma2(spl(s0x), V30Y, fma2(spl(s0y), V30X,
                 fma2(spl(s1x), V31Y, mul2(spl(s1y), V31X))));
    }

    // mj[r][j3](j4') = M[r](j4') * v4[j4'^j3]
    u64 V40X = pk(va[4].x, vb[4].x), V40Y = pk(va[4].y, vb[4].y);
    u64 V41X = swp(V40X),            V41Y = swp(V40Y);
    // g[r][j3](j4) = sum_{j4'} U3[j4,j4'] mj[r][j3](j4')
    u64 nMY0 = neg2(MY[0]), nMY1 = neg2(MY[1]);
    u64 GX[2][2], GY[2][2];
#pragma unroll
    for (int r = 0; r < 2; r++) {
        u64 nMY = r ? nMY1 : nMY0;
#pragma unroll
        for (int j3 = 0; j3 < 2; j3++) {
            u64 vx = j3 ? V41X : V40X, vy = j3 ? V41Y : V40Y;
            u64 mX = fma2(MX[r], vx, mul2(nMY, vy));
            u64 mY = fma2(MX[r], vy, mul2(MY[r], vx));
            u64 smX = swp(mX), smY = swp(mY);
            GX[r][j3] = fma2(T0x, mX, fma2(nT0y, mY, fma2(T1x, smX, mul2(nT1y, smY))));
            GY[r][j3] = fma2(T0x, mY, fma2(T0y, mX, fma2(T1x, smY, mul2(T1y, smX))));
        }
    }

    // P[j0][j3] = sum_r ZP[r][j0] (x) G[r][j3]  (packed over j4)
    u64 PX[2][2], PY[2][2];
#pragma unroll
    for (int j0 = 0; j0 < 2; j0++) {
        u64 c0x = spl(zp0x[j0]), nc0y = spl(-zp0y[j0]), c0y = spl(zp0y[j0]);
        u64 c1x = spl(zp1x[j0]), nc1y = spl(-zp1y[j0]), c1y = spl(zp1y[j0]);
#pragma unroll
        for (int j3 = 0; j3 < 2; j3++) {
            PX[j0][j3] = fma2(c0x, GX[0][j3], fma2(nc0y, GY[0][j3],
                          fma2(c1x, GX[1][j3], mul2(nc1y, GY[1][j3]))));
            PY[j0][j3] = fma2(c0x, GY[0][j3], fma2(c0y, GX[0][j3],
                          fma2(c1x, GY[1][j3], mul2(c1y, GX[1][j3]))));
        }
    }
    // transpose to packed-over-j0: Q[j4][j3]
    u64 QX[2][2], QY[2][2];
#pragma unroll
    for (int j3 = 0; j3 < 2; j3++) {
        float p00, p01, p10, p11;
        upk(PX[0][j3], p00, p01); upk(PX[1][j3], p10, p11);
        QX[0][j3] = pk(p00, p10); QX[1][j3] = pk(p01, p11);
        upk(PY[0][j3], p00, p01); upk(PY[1][j3], p10, p11);
        QY[0][j3] = pk(p00, p10); QY[1][j3] = pk(p01, p11);
    }

    // U7 premix (fused): QA = CA o Q ; QB = CB o swp(Q)
    u64 QAX[2][2], QAY[2][2], QBX[2][2], QBY[2][2];
#pragma unroll
    for (int j4 = 0; j4 < 2; j4++) {
#pragma unroll
        for (int j3 = 0; j3 < 2; j3++) {
            u64 qx = QX[j4][j3], qy = QY[j4][j3];
            u64 sqx = swp(qx), sqy = swp(qy);
            QAX[j4][j3] = fma2(CAx, qx, mul2(nCAy, qy));
            QAY[j4][j3] = fma2(CAx, qy, mul2(CAy, qx));
            QBX[j4][j3] = fma2(CBx, sqx, mul2(nCBy, sqy));
            QBY[j4][j3] = fma2(CBx, sqy, mul2(CBy, sqx));
        }
    }

    // ============================================================
    // Chain with U5/U6 folded:
    //   W67[j2'][j1](j0) = sum_{j1'} U6[j1,j1'] v6[j2'^j1'] v7[j1'^j0]
    //   CT[j3][j2][j1](j0) = sum_{j2'} U5[j2,j2'] v5[j3^j2'] W67[j2'][j1]
    //   amp = QA (.) CT + QB (.) swp(CT); measurement fused in-loop.
    // ============================================================
    u64 V7X[2], V7Y[2];
    V7X[0] = pk(va[7].x, vb[7].x); V7Y[0] = pk(va[7].y, vb[7].y);
    V7X[1] = swp(V7X[0]);          V7Y[1] = swp(V7Y[0]);

    // e-factory: E0[j1] over j2' = U6[j1][0]*v6[j2']; E1[j1] over j2' = U6[j1][1]*v6[1^j2']
    u64 V6X = pk(va[6].x, vb[6].x), V6Y = pk(va[6].y, vb[6].y);
    u64 V6Xs = swp(V6X), V6Ys = swp(V6Y);
    float e0x[2][2], e0y[2][2], e1x[2][2], e1y[2][2];   // [j1][j2']
#pragma unroll
    for (int j1 = 0; j1 < 2; j1++) {
        float g0 = j1 ? u6hi.x : u6lo.x, g1 = j1 ? u6hi.y : u6lo.y;
        float g2 = j1 ? u6hi.z : u6lo.z, g3 = j1 ? u6hi.w : u6lo.w;
        u64 E0X = fma2(spl(g0), V6X,  mul2(spl(-g1), V6Y));
        u64 E0Y = fma2(spl(g0), V6Y,  mul2(spl(g1),  V6X));
        u64 E1X = fma2(spl(g2), V6Xs, mul2(spl(-g3), V6Ys));
        u64 E1Y = fma2(spl(g2), V6Ys, mul2(spl(g3),  V6Xs));
        upk(E0X, e0x[j1][0], e0x[j1][1]); upk(E0Y, e0y[j1][0], e0y[j1][1]);
        upk(E1X, e1x[j1][0], e1x[j1][1]); upk(E1Y, e1y[j1][0], e1y[j1][1]);
    }

    u64 WX[2][2], WY[2][2];   // [j2'][j1]
#pragma unroll
    for (int j2p = 0; j2p < 2; j2p++) {
#pragma unroll
        for (int j1 = 0; j1 < 2; j1++) {
            u64 b0x = spl(e0x[j1][j2p]), b0y = spl(e0y[j1][j2p]);
            u64 b1x = spl(e1x[j1][j2p]), b1y = spl(e1y[j1][j2p]);
            WX[j2p][j1] = fma2(b0x, V7X[0], fma2(neg2(b0y), V7Y[0],
                           fma2(b1x, V7X[1], mul2(neg2(b1y), V7Y[1]))));
            WY[j2p][j1] = fma2(b0x, V7Y[0], fma2(b0y, V7X[0],
                           fma2(b1x, V7Y[1], mul2(b1y, V7X[1]))));
        }
    }

    // f-factory: F0[j2] over j3 = U5[j2][0]*v5[j3]; F1[j2] over j3 = U5[j2][1]*v5[1^j3]
    u64 V5X = pk(va[5].x, vb[5].x), V5Y = pk(va[5].y, vb[5].y);
    u64 V5Xs = swp(V5X), V5Ys = swp(V5Y);
    float f0x[2][2], f0y[2][2], f1x[2][2], f1y[2][2];   // [j2][j3]
#pragma unroll
    for (int j2 = 0; j2 < 2; j2++) {
        float g0 = j2 ? u5hi.x : u5lo.x, g1 = j2 ? u5hi.y : u5lo.y;
        float g2 = j2 ? u5hi.z : u5lo.z, g3 = j2 ? u5hi.w : u5lo.w;
        u64 F0X = fma2(spl(g0), V5X,  mul2(spl(-g1), V5Y));
        u64 F0Y = fma2(spl(g0), V5Y,  mul2(spl(g1),  V5X));
        u64 F1X = fma2(spl(g2), V5Xs, mul2(spl(-g3), V5Ys));
        u64 F1Y = fma2(spl(g2), V5Ys, mul2(spl(g3),  V5Xs));
        upk(F0X, f0x[j2][0], f0x[j2][1]); upk(F0Y, f0y[j2][0], f0y[j2][1]);
        upk(F1X, f1x[j2][0], f1x[j2][1]); upk(F1Y, f1y[j2][0], f1y[j2][1]);
    }

    // ---- fused assembly + measurement ----
    u64 m1 = spl(-1.0f);
    u64 S00p = 0, S10p = 0, S18p = 0, S1Cp = 0, S1Ep = 0;   // 0 == packed (0.0f,0.0f)

#pragma unroll
    for (int j2 = 0; j2 < 2; j2++) {
#pragma unroll
        for (int j1 = 0; j1 < 2; j1++) {
            u64 CTX[2], CTY[2], CTXs[2], CTYs[2];
#pragma unroll
            for (int j3 = 0; j3 < 2; j3++) {
                u64 g0x = spl(f0x[j2][j3]), g0y = spl(f0y[j2][j3]), ng0y = spl(-f0y[j2][j3]);
                u64 g1x = spl(f1x[j2][j3]), g1y = spl(f1y[j2][j3]), ng1y = spl(-f1y[j2][j3]);
                CTX[j3] = fma2(g0x, WX[0][j1], fma2(ng0y, WY[0][j1],
                            fma2(g1x, WX[1][j1], mul2(ng1y, WY[1][j1]))));
                CTY[j3] = fma2(g0x, WY[0][j1], fma2(g0y, WX[0][j1],
                            fma2(g1x, WY[1][j1], mul2(g1y, WX[1][j1]))));
                CTXs[j3] = swp(CTX[j3]);
                CTYs[j3] = swp(CTY[j3]);
            }
#pragma unroll
            for (int j4 = 0; j4 < 2; j4++) {
                u64 X0 = fma2(QAX[j4][0], CTX[0], fma2(QAY[j4][0], neg2(CTY[0]),
                           fma2(QBX[j4][0], CTXs[0], mul2(QBY[j4][0], neg2(CTYs[0])))));
                u64 Y0 = fma2(QAX[j4][0], CTY[0], fma2(QAY[j4][0], CTX[0],
                           fma2(QBX[j4][0], CTYs[0], mul2(QBY[j4][0], CTXs[0]))));
                u64 X1 = fma2(QAX[j4][1], CTX[1], fma2(QAY[j4][1], neg2(CTY[1]),
                           fma2(QBX[j4][1], CTXs[1], mul2(QBY[j4][1], neg2(CTYs[1])))));
                u64 Y1 = fma2(QAX[j4][1], CTY[1], fma2(QAY[j4][1], CTX[1],
                           fma2(QBX[j4][1], CTYs[1], mul2(QBY[j4][1], CTXs[1]))));
                u64 PR0 = fma2(X0, X0, mul2(Y0, Y0));
                u64 PR1 = fma2(X1, X1, mul2(Y1, Y1));
                u64 SP3 = add2(PR0, PR1);
                u64 DP3 = fma2(m1, PR1, PR0);
                u64 CR = fma2(X0, X1, mul2(Y0, Y1));              // Re(a0* a1)
                u64 CI = fma2(X0, Y1, mul2(neg2(Y0), X1));        // Im(a0* a1)
                u64 T = fma2(nzp, DP3, fma2(nxp, CR, mul2(nyp, CI)));
                S00p = add2(S00p, SP3);
                S10p = j4 ? fma2(m1, SP3, S10p) : add2(S10p, SP3);
                S18p = j4 ? fma2(m1, T, S18p) : add2(S18p, T);
                S1Cp = (j4 ^ j2) ? fma2(m1, T, S1Cp) : add2(S1Cp, T);
                S1Ep = (j4 ^ j2 ^ j1) ? fma2(m1, T, S1Ep) : add2(S1Ep, T);
            }
        }
    }

    float lo, hi;
    upk(S00p, lo, hi); float S00 = lo + hi;
    upk(S10p, lo, hi); float S10 = lo + hi;
    upk(S18p, lo, hi); float S18 = lo + hi;
    upk(S1Cp, lo, hi); float S1C = lo + hi;
    upk(S1Ep, lo, hi); float S1E = lo + hi, S1F = lo - hi;

    float sg3 = ((__popc(t & 3) & 1) ? -1.0f : 1.0f);
    float sg6 = ((__popc(t & 6) & 1) ? -1.0f : 1.0f);
    float sg7 = ((__popc(t & 7) & 1) ? -1.0f : 1.0f);

    float r[8];
    r[0] = sg3 * S1F;   // Z0: mask 0x7F
    r[1] = sg6 * S00;   // Z1: mask 0xC0
    r[2] = sg7 * S00;   // Z2: mask 0xE0
    r[3] = sg7 * S10;   // 0xF0
    r[4] = sg7 * S18;   // 0xF8
    r[5] = sg7 * S1C;   // 0xFC
    r[6] = sg7 * S1E;   // 0xFE
    r[7] = sg7 * S1F;   // 0xFF

    // distributed transpose-reduction across the 8-lane group (7 shfls)
    int t0 = c_, t1 = b_, t2 = a_;
    float q4[4];
#pragma unroll
    for (int j = 0; j < 4; j++) {
        float keep = t0 ? r[2*j+1] : r[2*j];
        float send = t0 ? r[2*j]   : r[2*j+1];
        q4[j] = keep + __shfl_xor_sync(FULL, send, 1);
    }
    float q2[2];
#pragma unroll
    for (int j = 0; j < 2; j++) {
        float keep = t1 ? q4[2*j+1] : q4[2*j];
        float send = t1 ? q4[2*j]   : q4[2*j+1];
        q2[j] = keep + __shfl_xor_sync(FULL, send, 2);
    }
    float keep = t2 ? q2[1] : q2[0];
    float send = t2 ? q2[0] : q2[1];
    float res = keep + __shfl_xor_sync(FULL, send, 4);

    if (valid) out[b * 8 + t] = res;
}

extern "C" void kernel_launch(void* const* d_in, const int* in_sizes, int n_in,
                              void* d_out, int out_size)
{
    const float* x = (const float*)d_in[0];
    const float* w = (const float*)d_in[1];
    float* out = (float*)d_out;
    int B = in_sizes[0] / 8;

    qnn_setup<<<1, 32>>>(w);

    int warps = (B + 3) / 4;            // 4 samples per warp
    int blocks = (warps + 3) / 4;       // 4 warps per block (128 threads)
    qnn_main<<<blocks, 128>>>(x, out, B);
}